// round 1
// baseline (speedup 1.0000x reference)
#include <cuda_runtime.h>
#include <math.h>

#define Bsz 512
#define Hd  1024
#define Od  512
#define KC  1536   // Od + Hd
#define G4  4096   // 4*Hd

// ---------------- scratch (static device allocations only) ----------------
__device__ float g_Xcat[Bsz * KC];   // [B][KC]: cols 0..511 = x (prev softmax y), 512..1535 = h
__device__ float g_c[Bsz * Hd];      // cell state
__device__ float g_Wcat[G4 * KC];    // [4H][KC] = [W_ih | W_hh], K-contiguous
__device__ float g_bias[G4];         // b_ih + b_hh
__device__ float g_gates[Bsz * G4];  // pre-activation gates scratch

// ---------------- prep kernels (run every launch: deterministic) ----------
__global__ void prep_weights(const float* __restrict__ W_ih,
                             const float* __restrict__ W_hh,
                             const float* __restrict__ b_ih,
                             const float* __restrict__ b_hh) {
    int idx = blockIdx.x * blockDim.x + threadIdx.x;
    if (idx < G4 * KC) {
        int j = idx / KC;
        int k = idx - j * KC;
        g_Wcat[idx] = (k < Od) ? W_ih[j * Od + k] : W_hh[j * Hd + (k - Od)];
    }
    if (idx < G4) g_bias[idx] = b_ih[idx] + b_hh[idx];
}

__global__ void prep_state(const float* __restrict__ h0,
                           const float* __restrict__ c0) {
    int idx = blockIdx.x * blockDim.x + threadIdx.x;
    if (idx < Bsz * Hd) {
        int b = idx >> 10;          // /Hd
        int j = idx & (Hd - 1);
        g_Xcat[b * KC + Od + j] = h0[idx];
        g_c[idx] = c0[idx];
    }
    if (idx < Bsz * Od) {
        int b = idx >> 9;           // /Od
        int k = idx & (Od - 1);
        g_Xcat[b * KC + k] = 0.0f;  // initial lstm input is zeros
    }
}

// ---------------- gates GEMM: g_gates[B,4H] = Xcat[B,KC] * Wcat^T + bias ----
#define MT 64
#define NT 64
#define KT 16

__global__ __launch_bounds__(256) void gemm_gates() {
    __shared__ float sA[KT][MT + 4];
    __shared__ float sB[KT][NT + 4];

    const int bm = blockIdx.y * MT;   // batch rows
    const int bn = blockIdx.x * NT;   // gate columns
    const int tid = threadIdx.x;

    const int lr = tid >> 2;          // 0..63 : tile row loaded by this thread
    const int lk = (tid & 3) << 2;    // 0,4,8,12 : k offset (float4)
    const int tr = (tid >> 4) << 2;   // 0..60 step 4 : micro-tile row base
    const int tc = (tid & 15) << 2;   // 0..60 step 4 : micro-tile col base

    float acc[4][4] = {};

    const float* Aptr = &g_Xcat[(bm + lr) * KC + lk];
    const float* Bptr = &g_Wcat[(bn + lr) * KC + lk];

    for (int k0 = 0; k0 < KC; k0 += KT) {
        float4 a = *(const float4*)(Aptr + k0);
        float4 b = *(const float4*)(Bptr + k0);
        sA[lk + 0][lr] = a.x; sA[lk + 1][lr] = a.y;
        sA[lk + 2][lr] = a.z; sA[lk + 3][lr] = a.w;
        sB[lk + 0][lr] = b.x; sB[lk + 1][lr] = b.y;
        sB[lk + 2][lr] = b.z; sB[lk + 3][lr] = b.w;
        __syncthreads();

        #pragma unroll
        for (int kk = 0; kk < KT; kk++) {
            float av[4], bv[4];
            #pragma unroll
            for (int i = 0; i < 4; i++) av[i] = sA[kk][tr + i];
            #pragma unroll
            for (int j = 0; j < 4; j++) bv[j] = sB[kk][tc + j];
            #pragma unroll
            for (int i = 0; i < 4; i++)
                #pragma unroll
                for (int j = 0; j < 4; j++)
                    acc[i][j] = fmaf(av[i], bv[j], acc[i][j]);
        }
        __syncthreads();
    }

    #pragma unroll
    for (int i = 0; i < 4; i++) {
        #pragma unroll
        for (int j = 0; j < 4; j++) {
            int col = bn + tc + j;
            g_gates[(bm + tr + i) * G4 + col] = acc[i][j] + g_bias[col];
        }
    }
}

// ---------------- LSTM cell update --------------------------------------
__device__ __forceinline__ float sigm(float x) { return 1.0f / (1.0f + expf(-x)); }

__global__ void cell_update() {
    int idx = blockIdx.x * blockDim.x + threadIdx.x;   // Bsz*Hd threads
    int b = idx >> 10;
    int j = idx & (Hd - 1);
    const float* g = &g_gates[b * G4];
    float gi = g[j];
    float gf = g[Hd + j];
    float gg = g[2 * Hd + j];
    float go = g[3 * Hd + j];
    float c  = g_c[idx];
    float cn = sigm(gf) * c + sigm(gi) * tanhf(gg);
    g_c[idx] = cn;
    g_Xcat[b * KC + Od + j] = sigm(go) * tanhf(cn);   // h_new
}

// ---------------- output projection + softmax ----------------------------
// One block handles RB=8 batch rows x all 512 columns. Each thread owns 2 cols.
#define RB 8

__global__ __launch_bounds__(256) void out_step(const float* __restrict__ W_out,
                                                const float* __restrict__ b_out,
                                                float* __restrict__ out,
                                                int step_off) {
    __shared__ float sh[RB][Hd];     // 32 KB of h rows
    __shared__ float red[RB][8];

    const int b0 = blockIdx.x * RB;
    const int tid = threadIdx.x;
    const int warp = tid >> 5, lane = tid & 31;

    for (int i = tid; i < RB * Hd; i += 256) {
        int r = i >> 10, k = i & (Hd - 1);
        sh[r][k] = g_Xcat[(b0 + r) * KC + Od + k];
    }
    __syncthreads();

    const int c0 = tid;
    const int c1 = tid + 256;
    float acc0[RB] = {}, acc1[RB] = {};
    const float4* w0 = (const float4*)&W_out[c0 * Hd];
    const float4* w1 = (const float4*)&W_out[c1 * Hd];

    for (int k4 = 0; k4 < Hd / 4; k4++) {
        float4 a = w0[k4];
        float4 bw = w1[k4];
        #pragma unroll
        for (int r = 0; r < RB; r++) {
            float4 hv = *(const float4*)&sh[r][k4 * 4];
            acc0[r] += hv.x * a.x + hv.y * a.y + hv.z * a.z + hv.w * a.w;
            acc1[r] += hv.x * bw.x + hv.y * bw.y + hv.z * bw.z + hv.w * bw.w;
        }
    }

    const float bo0 = b_out[c0];
    const float bo1 = b_out[c1];

    // row-wise max
    #pragma unroll
    for (int r = 0; r < RB; r++) {
        acc0[r] += bo0;
        acc1[r] += bo1;
        float mm = fmaxf(acc0[r], acc1[r]);
        #pragma unroll
        for (int o = 16; o; o >>= 1) mm = fmaxf(mm, __shfl_xor_sync(0xffffffffu, mm, o));
        if (lane == 0) red[r][warp] = mm;
    }
    __syncthreads();
    float m[RB];
    #pragma unroll
    for (int r = 0; r < RB; r++) {
        float mm = red[r][0];
        #pragma unroll
        for (int w = 1; w < 8; w++) mm = fmaxf(mm, red[r][w]);
        m[r] = mm;
    }
    __syncthreads();

    // exp + row-wise sum
    #pragma unroll
    for (int r = 0; r < RB; r++) {
        acc0[r] = expf(acc0[r] - m[r]);
        acc1[r] = expf(acc1[r] - m[r]);
        float ss = acc0[r] + acc1[r];
        #pragma unroll
        for (int o = 16; o; o >>= 1) ss += __shfl_xor_sync(0xffffffffu, ss, o);
        if (lane == 0) red[r][warp] = ss;
    }
    __syncthreads();

    #pragma unroll
    for (int r = 0; r < RB; r++) {
        float ss = 0.0f;
        #pragma unroll
        for (int w = 0; w < 8; w++) ss += red[r][w];
        float inv = 1.0f / ss;
        float y0 = acc0[r] * inv;
        float y1 = acc1[r] * inv;
        int b = b0 + r;
        out[step_off + b * Od + c0] = y0;
        out[step_off + b * Od + c1] = y1;
        g_Xcat[b * KC + c0] = y0;    // feeds next step's GEMM
        g_Xcat[b * KC + c1] = y1;
    }
}

// ---------------- launcher ------------------------------------------------
extern "C" void kernel_launch(void* const* d_in, const int* in_sizes, int n_in,
                              void* d_out, int out_size) {
    const float* h0    = (const float*)d_in[0];
    const float* c0    = (const float*)d_in[1];
    const float* W_ih  = (const float*)d_in[2];
    const float* W_hh  = (const float*)d_in[3];
    const float* b_ih  = (const float*)d_in[4];
    const float* b_hh  = (const float*)d_in[5];
    const float* W_out = (const float*)d_in[6];
    const float* b_out = (const float*)d_in[7];
    float* out = (float*)d_out;

    const int T = out_size / (Bsz * Od);   // cannot sync-read out_len under capture

    prep_weights<<<(G4 * KC + 255) / 256, 256>>>(W_ih, W_hh, b_ih, b_hh);
    prep_state<<<(Bsz * Hd + 255) / 256, 256>>>(h0, c0);

    dim3 ggrid(G4 / NT, Bsz / MT);   // (64, 8)
    for (int t = 0; t < T; t++) {
        gemm_gates<<<ggrid, 256>>>();
        cell_update<<<(Bsz * Hd) / 256, 256>>>();
        out_step<<<Bsz / RB, 256>>>(W_out, b_out, out, (T - 1 - t) * Bsz * Od);
    }
}

// round 2
// speedup vs baseline: 1.6029x; 1.6029x over previous
#include <cuda_runtime.h>
#include <cuda_bf16.h>
#include <math.h>

#define Bsz 512
#define Hd  1024
#define Od  512
#define KC  1536   // Od + Hd
#define G4  4096   // 4*Hd

// ---------------- scratch ----------------
__device__ __nv_bfloat16 g_Xh[Bsz * KC];   // hi(x|h)
__device__ __nv_bfloat16 g_Xl[Bsz * KC];   // lo(x|h)
__device__ __nv_bfloat16 g_Wh[G4 * KC];    // hi([W_ih|W_hh])
__device__ __nv_bfloat16 g_Wl[G4 * KC];    // lo
__device__ float g_c[Bsz * Hd];
__device__ float g_bias[G4];
__device__ float g_gates[Bsz * G4];

__device__ __forceinline__ void split_bf16(float v, __nv_bfloat16& hi, __nv_bfloat16& lo) {
    hi = __float2bfloat16(v);
    lo = __float2bfloat16(v - __bfloat162float(hi));
}

// ---------------- prep -------------------
__global__ void prep_weights(const float* __restrict__ W_ih,
                             const float* __restrict__ W_hh,
                             const float* __restrict__ b_ih,
                             const float* __restrict__ b_hh) {
    int idx = blockIdx.x * blockDim.x + threadIdx.x;
    if (idx < G4 * KC) {
        int j = idx / KC;
        int k = idx - j * KC;
        float w = (k < Od) ? W_ih[j * Od + k] : W_hh[j * Hd + (k - Od)];
        __nv_bfloat16 hi, lo;
        split_bf16(w, hi, lo);
        g_Wh[idx] = hi;
        g_Wl[idx] = lo;
    }
    if (idx < G4) g_bias[idx] = b_ih[idx] + b_hh[idx];
}

__global__ void prep_state(const float* __restrict__ h0,
                           const float* __restrict__ c0) {
    int idx = blockIdx.x * blockDim.x + threadIdx.x;
    if (idx < Bsz * Hd) {
        int b = idx >> 10;
        int j = idx & (Hd - 1);
        __nv_bfloat16 hi, lo;
        split_bf16(h0[idx], hi, lo);
        g_Xh[b * KC + Od + j] = hi;
        g_Xl[b * KC + Od + j] = lo;
        g_c[idx] = c0[idx];
    }
    if (idx < Bsz * Od) {
        int b = idx >> 9;
        int k = idx & (Od - 1);
        g_Xh[b * KC + k] = __float2bfloat16(0.0f);
        g_Xl[b * KC + k] = __float2bfloat16(0.0f);
    }
}

// ---------------- tensor-core gates GEMM ---------------------------------
// gates[512,4096] = X[512,1536] @ W[4096,1536]^T via 3 bf16-split passes:
//   (Xh,Wh) + (Xh,Wl) + (Xl,Wh), fp32 accumulate.
// BM=128, BN=128, BK=32, 256 threads (8 warps, 2x4), warp tile 64x32.

#define SWZ(b) ((b) ^ (((b) >> 3) & 0x30))   // 64B-row XOR swizzle

#define CP_ASYNC16(dst, src) asm volatile("cp.async.cg.shared.global [%0], [%1], 16;\n" :: "r"(dst), "l"(src))
#define CP_COMMIT            asm volatile("cp.async.commit_group;\n")
#define CP_WAIT1             asm volatile("cp.async.wait_group 1;\n")
#define CP_WAIT0             asm volatile("cp.async.wait_group 0;\n")

#define NTILES 144   // 3 passes * 48 k-tiles

__global__ __launch_bounds__(256) void gemm_gates_mma() {
    __shared__ __align__(1024) unsigned char sm[2][16384];   // [buf]: A 8KB | B 8KB

    const int tid  = threadIdx.x;
    const int wid  = tid >> 5;
    const int lane = tid & 31;
    const int warp_m = wid >> 2;     // 0..1
    const int warp_n = wid & 3;      // 0..3
    const int bm = blockIdx.y * 128;
    const int bn = blockIdx.x * 128;

    const unsigned sbase = (unsigned)__cvta_generic_to_shared(&sm[0][0]);

    // per-thread load descriptors: chunk id t and t+256; row=id>>2, kc=id&3
    const int rA0 = tid >> 2;
    const int rA1 = rA0 + 64;
    const int kc  = tid & 3;
    const unsigned sOff0 = SWZ((unsigned)(rA0 * 64 + kc * 16));
    const unsigned sOff1 = SWZ((unsigned)(rA1 * 64 + kc * 16));

    float acc[4][4][4];
    #pragma unroll
    for (int i = 0; i < 4; i++)
        #pragma unroll
        for (int j = 0; j < 4; j++)
            #pragma unroll
            for (int q = 0; q < 4; q++) acc[i][j][q] = 0.0f;

    // ---- tile loader ----
    #define LOAD_TILE(I, BUF) do {                                            \
        int p_  = (I) / 48;                                                   \
        int k0_ = ((I) % 48) * 32;                                            \
        const __nv_bfloat16* Ag_ = (p_ == 2) ? g_Xl : g_Xh;                   \
        const __nv_bfloat16* Bg_ = (p_ == 1) ? g_Wl : g_Wh;                   \
        unsigned ab_ = sbase + (BUF) * 16384;                                 \
        unsigned bb_ = ab_ + 8192;                                            \
        CP_ASYNC16(ab_ + sOff0, Ag_ + (size_t)(bm + rA0) * KC + k0_ + kc * 8);\
        CP_ASYNC16(ab_ + sOff1, Ag_ + (size_t)(bm + rA1) * KC + k0_ + kc * 8);\
        CP_ASYNC16(bb_ + sOff0, Bg_ + (size_t)(bn + rA0) * KC + k0_ + kc * 8);\
        CP_ASYNC16(bb_ + sOff1, Bg_ + (size_t)(bn + rA1) * KC + k0_ + kc * 8);\
    } while (0)

    LOAD_TILE(0, 0);
    CP_COMMIT;

    for (int it = 0; it < NTILES; it++) {
        const int buf = it & 1;
        if (it + 1 < NTILES) {
            LOAD_TILE(it + 1, buf ^ 1);
            CP_COMMIT;
            CP_WAIT1;
        } else {
            CP_WAIT0;
        }
        __syncthreads();

        const unsigned ab = sbase + buf * 16384;
        const unsigned bb = ab + 8192;

        #pragma unroll
        for (int kk = 0; kk < 2; kk++) {
            // A fragments: 4 m-frags of 16 rows
            unsigned ar  = (unsigned)(lane & 15);
            unsigned ahk = (unsigned)(lane >> 4);      // 0/1 -> k half
            unsigned a_[4][4];
            #pragma unroll
            for (int mf = 0; mf < 4; mf++) {
                unsigned byte = (warp_m * 64 + mf * 16 + ar) * 64 + kk * 32 + ahk * 16;
                unsigned addr = ab + SWZ(byte);
                asm volatile("ldmatrix.sync.aligned.m8n8.x4.shared.b16 {%0,%1,%2,%3}, [%4];"
                             : "=r"(a_[mf][0]), "=r"(a_[mf][1]), "=r"(a_[mf][2]), "=r"(a_[mf][3])
                             : "r"(addr));
            }
            // B fragments: 4 n-frags of 8 cols (two x4 loads covering 16 cols each)
            unsigned b_[4][2];
            #pragma unroll
            for (int pr = 0; pr < 2; pr++) {
                unsigned n = warp_n * 32 + pr * 16 + (lane & 7) + ((lane >> 4) & 1) * 8;
                unsigned byte = n * 64 + kk * 32 + ((lane >> 3) & 1) * 16;
                unsigned addr = bb + SWZ(byte);
                unsigned r0, r1, r2, r3;
                asm volatile("ldmatrix.sync.aligned.m8n8.x4.shared.b16 {%0,%1,%2,%3}, [%4];"
                             : "=r"(r0), "=r"(r1), "=r"(r2), "=r"(r3)
                             : "r"(addr));
                b_[2 * pr][0] = r0;  b_[2 * pr][1] = r1;
                b_[2 * pr + 1][0] = r2;  b_[2 * pr + 1][1] = r3;
            }
            #pragma unroll
            for (int mf = 0; mf < 4; mf++)
                #pragma unroll
                for (int nf = 0; nf < 4; nf++) {
                    asm volatile(
                        "mma.sync.aligned.m16n8k16.row.col.f32.bf16.bf16.f32 "
                        "{%0,%1,%2,%3}, {%4,%5,%6,%7}, {%8,%9}, {%0,%1,%2,%3};"
                        : "+f"(acc[mf][nf][0]), "+f"(acc[mf][nf][1]),
                          "+f"(acc[mf][nf][2]), "+f"(acc[mf][nf][3])
                        : "r"(a_[mf][0]), "r"(a_[mf][1]), "r"(a_[mf][2]), "r"(a_[mf][3]),
                          "r"(b_[nf][0]), "r"(b_[nf][1]));
                }
        }
        __syncthreads();
    }

    // epilogue: + bias, fp32 store
    #pragma unroll
    for (int mf = 0; mf < 4; mf++) {
        #pragma unroll
        for (int nf = 0; nf < 4; nf++) {
            int row = bm + warp_m * 64 + mf * 16 + (lane >> 2);
            int col = bn + warp_n * 32 + nf * 8 + (lane & 3) * 2;
            float b0 = g_bias[col], b1 = g_bias[col + 1];
            float2 v0 = make_float2(acc[mf][nf][0] + b0, acc[mf][nf][1] + b1);
            float2 v1 = make_float2(acc[mf][nf][2] + b0, acc[mf][nf][3] + b1);
            *(float2*)&g_gates[(size_t)row * G4 + col] = v0;
            *(float2*)&g_gates[(size_t)(row + 8) * G4 + col] = v1;
        }
    }
}

// ---------------- fused cell update + output projection + softmax --------
__device__ __forceinline__ float sigm(float x) { return 1.0f / (1.0f + expf(-x)); }

#define RB 8

__global__ __launch_bounds__(256) void out_step(const float* __restrict__ W_out,
                                                const float* __restrict__ b_out,
                                                float* __restrict__ out,
                                                int step_off) {
    __shared__ float sh[RB][Hd];
    __shared__ float red[RB][8];

    const int b0 = blockIdx.x * RB;
    const int tid = threadIdx.x;
    const int warp = tid >> 5, lane = tid & 31;

    // --- fused LSTM cell update for this block's 8 rows ---
    for (int i = tid; i < RB * Hd; i += 256) {
        int r = i >> 10, j = i & (Hd - 1);
        int b = b0 + r;
        const float* g = &g_gates[(size_t)b * G4];
        float gi = g[j];
        float gf = g[Hd + j];
        float gg = g[2 * Hd + j];
        float go = g[3 * Hd + j];
        float c = g_c[b * Hd + j];
        float cn = sigm(gf) * c + sigm(gi) * tanhf(gg);
        g_c[b * Hd + j] = cn;
        float hn = sigm(go) * tanhf(cn);
        sh[r][j] = hn;
        __nv_bfloat16 hi, lo;
        split_bf16(hn, hi, lo);
        g_Xh[b * KC + Od + j] = hi;
        g_Xl[b * KC + Od + j] = lo;
    }
    __syncthreads();

    // --- projection: each thread owns 2 output columns ---
    const int c0 = tid;
    const int c1 = tid + 256;
    float acc0[RB] = {}, acc1[RB] = {};
    const float4* w0 = (const float4*)&W_out[(size_t)c0 * Hd];
    const float4* w1 = (const float4*)&W_out[(size_t)c1 * Hd];

    for (int k4 = 0; k4 < Hd / 4; k4++) {
        float4 a = w0[k4];
        float4 bw = w1[k4];
        #pragma unroll
        for (int r = 0; r < RB; r++) {
            float4 hv = *(const float4*)&sh[r][k4 * 4];
            acc0[r] += hv.x * a.x + hv.y * a.y + hv.z * a.z + hv.w * a.w;
            acc1[r] += hv.x * bw.x + hv.y * bw.y + hv.z * bw.z + hv.w * bw.w;
        }
    }

    const float bo0 = b_out[c0];
    const float bo1 = b_out[c1];

    #pragma unroll
    for (int r = 0; r < RB; r++) {
        acc0[r] += bo0;
        acc1[r] += bo1;
        float mm = fmaxf(acc0[r], acc1[r]);
        #pragma unroll
        for (int o = 16; o; o >>= 1) mm = fmaxf(mm, __shfl_xor_sync(0xffffffffu, mm, o));
        if (lane == 0) red[r][warp] = mm;
    }
    __syncthreads();
    float m[RB];
    #pragma unroll
    for (int r = 0; r < RB; r++) {
        float mm = red[r][0];
        #pragma unroll
        for (int w = 1; w < 8; w++) mm = fmaxf(mm, red[r][w]);
        m[r] = mm;
    }
    __syncthreads();

    #pragma unroll
    for (int r = 0; r < RB; r++) {
        acc0[r] = expf(acc0[r] - m[r]);
        acc1[r] = expf(acc1[r] - m[r]);
        float ss = acc0[r] + acc1[r];
        #pragma unroll
        for (int o = 16; o; o >>= 1) ss += __shfl_xor_sync(0xffffffffu, ss, o);
        if (lane == 0) red[r][warp] = ss;
    }
    __syncthreads();

    #pragma unroll
    for (int r = 0; r < RB; r++) {
        float ss = 0.0f;
        #pragma unroll
        for (int w = 0; w < 8; w++) ss += red[r][w];
        float inv = 1.0f / ss;
        float y0 = acc0[r] * inv;
        float y1 = acc1[r] * inv;
        int b = b0 + r;
        out[step_off + b * Od + c0] = y0;
        out[step_off + b * Od + c1] = y1;
        __nv_bfloat16 hi, lo;
        split_bf16(y0, hi, lo);
        g_Xh[b * KC + c0] = hi;  g_Xl[b * KC + c0] = lo;
        split_bf16(y1, hi, lo);
        g_Xh[b * KC + c1] = hi;  g_Xl[b * KC + c1] = lo;
    }
}

// ---------------- launcher ------------------------------------------------
extern "C" void kernel_launch(void* const* d_in, const int* in_sizes, int n_in,
                              void* d_out, int out_size) {
    const float* h0    = (const float*)d_in[0];
    const float* c0    = (const float*)d_in[1];
    const float* W_ih  = (const float*)d_in[2];
    const float* W_hh  = (const float*)d_in[3];
    const float* b_ih  = (const float*)d_in[4];
    const float* b_hh  = (const float*)d_in[5];
    const float* W_out = (const float*)d_in[6];
    const float* b_out = (const float*)d_in[7];
    float* out = (float*)d_out;

    const int T = out_size / (Bsz * Od);

    prep_weights<<<(G4 * KC + 255) / 256, 256>>>(W_ih, W_hh, b_ih, b_hh);
    prep_state<<<(Bsz * Hd + 255) / 256, 256>>>(h0, c0);

    dim3 ggrid(G4 / 128, Bsz / 128);   // (32, 4) = 128 blocks
    for (int t = 0; t < T; t++) {
        gemm_gates_mma<<<ggrid, 256>>>();
        out_step<<<Bsz / RB, 256>>>(W_out, b_out, out, (T - 1 - t) * Bsz * Od);
    }
}

// round 3
// speedup vs baseline: 2.2101x; 1.3788x over previous
#include <cuda_runtime.h>
#include <cuda_bf16.h>
#include <math.h>

#define Bsz 512
#define Hd  1024
#define Od  512
#define KC  1536   // Od + Hd
#define G4  4096   // 4*Hd

// ---------------- scratch ----------------
// X buffers are ping-ponged per step: [buf][B][KC], cols 0..511 = x, 512..1535 = h
__device__ __nv_bfloat16 g_Xh[2][Bsz * KC];
__device__ __nv_bfloat16 g_Xl[2][Bsz * KC];
__device__ __nv_bfloat16 g_Wh[G4 * KC];    // gate-interleaved [4j+gate][k] hi
__device__ __nv_bfloat16 g_Wl[G4 * KC];    // lo
__device__ __nv_bfloat16 g_Woh[Od * Hd];   // W_out hi
__device__ __nv_bfloat16 g_Wol[Od * Hd];   // W_out lo
__device__ float g_c[Bsz * Hd];
__device__ float g_bias[G4];               // gate-interleaved bias
__device__ float g_logits[Bsz * Od];

__device__ __forceinline__ void split_bf16(float v, __nv_bfloat16& hi, __nv_bfloat16& lo) {
    hi = __float2bfloat16(v);
    lo = __float2bfloat16(v - __bfloat162float(hi));
}

__device__ __forceinline__ float sigm(float x) { return 1.0f / (1.0f + __expf(-x)); }
__device__ __forceinline__ float ftanh(float x) { return 1.0f - 2.0f / (__expf(2.0f * x) + 1.0f); }

// ---------------- prep -------------------
__global__ void prep_weights(const float* __restrict__ W_ih,
                             const float* __restrict__ W_hh,
                             const float* __restrict__ b_ih,
                             const float* __restrict__ b_hh,
                             const float* __restrict__ W_out) {
    int idx = blockIdx.x * blockDim.x + threadIdx.x;
    if (idx < G4 * KC) {
        int r = idx / KC;            // interleaved row: 4j+gate
        int k = idx - r * KC;
        int j = r >> 2, gate = r & 3;
        int orow = gate * Hd + j;    // original row in [W_ih|W_hh]
        float w = (k < Od) ? W_ih[orow * Od + k] : W_hh[orow * Hd + (k - Od)];
        __nv_bfloat16 hi, lo;
        split_bf16(w, hi, lo);
        g_Wh[idx] = hi;
        g_Wl[idx] = lo;
    }
    if (idx < G4) {
        int j = idx >> 2, gate = idx & 3;
        g_bias[idx] = b_ih[gate * Hd + j] + b_hh[gate * Hd + j];
    }
    if (idx < Od * Hd) {
        __nv_bfloat16 hi, lo;
        split_bf16(W_out[idx], hi, lo);
        g_Woh[idx] = hi;
        g_Wol[idx] = lo;
    }
}

__global__ void prep_state(const float* __restrict__ h0,
                           const float* __restrict__ c0) {
    int idx = blockIdx.x * blockDim.x + threadIdx.x;
    if (idx < Bsz * Hd) {
        int b = idx >> 10;
        int j = idx & (Hd - 1);
        __nv_bfloat16 hi, lo;
        split_bf16(h0[idx], hi, lo);
        g_Xh[0][b * KC + Od + j] = hi;
        g_Xl[0][b * KC + Od + j] = lo;
        g_c[idx] = c0[idx];
    }
    if (idx < Bsz * Od) {
        int b = idx >> 9;
        int k = idx & (Od - 1);
        g_Xh[0][b * KC + k] = __float2bfloat16(0.0f);
        g_Xl[0][b * KC + k] = __float2bfloat16(0.0f);
    }
}

// ---------------- common asm helpers --------------------------------------
#define SWZ(b) ((b) ^ (((b) >> 3) & 0x30))

#define CP_ASYNC16(dst, src) asm volatile("cp.async.cg.shared.global [%0], [%1], 16;\n" :: "r"(dst), "l"(src))
#define CP_COMMIT            asm volatile("cp.async.commit_group;\n")
#define CP_WAIT2             asm volatile("cp.async.wait_group 2;\n")
#define CP_WAIT1             asm volatile("cp.async.wait_group 1;\n")
#define CP_WAIT0             asm volatile("cp.async.wait_group 0;\n")

// ==========================================================================
// gates GEMM + fused LSTM cell update
// gates[512,4096] = X[512,1536] @ Wperm[4096,1536]^T (3 bf16-split passes)
// then epilogue: cell update per hidden unit (gate-interleaved cols), writes
// g_c and h (bf16 split) into X buffer `wr`.
// BM=128 BN=128 BK=32, 8 warps (2x4), 3-stage cp.async pipeline.
// ==========================================================================
#define NT_GATES 144   // 3 passes * 48 k-tiles

__global__ __launch_bounds__(256) void gemm_gates_mma(int rd, int wr) {
    __shared__ __align__(1024) unsigned char sm[3][16384];   // per stage: A 8KB | B 8KB

    const int tid  = threadIdx.x;
    const int wid  = tid >> 5;
    const int lane = tid & 31;
    const int warp_m = wid >> 2;     // 0..1
    const int warp_n = wid & 3;      // 0..3
    const int bm = blockIdx.y * 128;
    const int bn = blockIdx.x * 128;

    const __nv_bfloat16* Xh = g_Xh[rd];
    const __nv_bfloat16* Xl = g_Xl[rd];

    const unsigned sbase = (unsigned)__cvta_generic_to_shared(&sm[0][0]);

    const int rA0 = tid >> 2;
    const int rA1 = rA0 + 64;
    const int kc  = tid & 3;
    const unsigned sOff0 = SWZ((unsigned)(rA0 * 64 + kc * 16));
    const unsigned sOff1 = SWZ((unsigned)(rA1 * 64 + kc * 16));

    float acc[4][4][4];
    #pragma unroll
    for (int i = 0; i < 4; i++)
        #pragma unroll
        for (int j = 0; j < 4; j++)
            #pragma unroll
            for (int q = 0; q < 4; q++) acc[i][j][q] = 0.0f;

    #define LOAD_TILE_G(I, BUF) do {                                          \
        int p_  = (I) / 48;                                                    \
        int k0_ = ((I) % 48) * 32;                                             \
        const __nv_bfloat16* Ag_ = (p_ == 2) ? Xl : Xh;                        \
        const __nv_bfloat16* Bg_ = (p_ == 1) ? g_Wl : g_Wh;                    \
        unsigned ab_ = sbase + (BUF) * 16384;                                  \
        unsigned bb_ = ab_ + 8192;                                             \
        CP_ASYNC16(ab_ + sOff0, Ag_ + (size_t)(bm + rA0) * KC + k0_ + kc * 8); \
        CP_ASYNC16(ab_ + sOff1, Ag_ + (size_t)(bm + rA1) * KC + k0_ + kc * 8); \
        CP_ASYNC16(bb_ + sOff0, Bg_ + (size_t)(bn + rA0) * KC + k0_ + kc * 8); \
        CP_ASYNC16(bb_ + sOff1, Bg_ + (size_t)(bn + rA1) * KC + k0_ + kc * 8); \
    } while (0)

    LOAD_TILE_G(0, 0); CP_COMMIT;
    LOAD_TILE_G(1, 1); CP_COMMIT;

    for (int it = 0; it < NT_GATES; it++) {
        const int buf = it % 3;
        if (it + 2 < NT_GATES) {
            LOAD_TILE_G(it + 2, (it + 2) % 3);
            CP_COMMIT;
            CP_WAIT2;
        } else if (it + 1 < NT_GATES) {
            CP_WAIT1;
        } else {
            CP_WAIT0;
        }
        __syncthreads();

        const unsigned ab = sbase + buf * 16384;
        const unsigned bb = ab + 8192;

        #pragma unroll
        for (int kk = 0; kk < 2; kk++) {
            unsigned ar  = (unsigned)(lane & 15);
            unsigned ahk = (unsigned)(lane >> 4);
            unsigned a_[4][4];
            #pragma unroll
            for (int mf = 0; mf < 4; mf++) {
                unsigned byte = (warp_m * 64 + mf * 16 + ar) * 64 + kk * 32 + ahk * 16;
                unsigned addr = ab + SWZ(byte);
                asm volatile("ldmatrix.sync.aligned.m8n8.x4.shared.b16 {%0,%1,%2,%3}, [%4];"
                             : "=r"(a_[mf][0]), "=r"(a_[mf][1]), "=r"(a_[mf][2]), "=r"(a_[mf][3])
                             : "r"(addr));
            }
            unsigned b_[4][2];
            #pragma unroll
            for (int pr = 0; pr < 2; pr++) {
                unsigned n = warp_n * 32 + pr * 16 + (lane & 7) + ((lane >> 4) & 1) * 8;
                unsigned byte = n * 64 + kk * 32 + ((lane >> 3) & 1) * 16;
                unsigned addr = bb + SWZ(byte);
                unsigned r0, r1, r2, r3;
                asm volatile("ldmatrix.sync.aligned.m8n8.x4.shared.b16 {%0,%1,%2,%3}, [%4];"
                             : "=r"(r0), "=r"(r1), "=r"(r2), "=r"(r3)
                             : "r"(addr));
                b_[2 * pr][0] = r0;      b_[2 * pr][1] = r1;
                b_[2 * pr + 1][0] = r2;  b_[2 * pr + 1][1] = r3;
            }
            #pragma unroll
            for (int mf = 0; mf < 4; mf++)
                #pragma unroll
                for (int nf = 0; nf < 4; nf++) {
                    asm volatile(
                        "mma.sync.aligned.m16n8k16.row.col.f32.bf16.bf16.f32 "
                        "{%0,%1,%2,%3}, {%4,%5,%6,%7}, {%8,%9}, {%0,%1,%2,%3};"
                        : "+f"(acc[mf][nf][0]), "+f"(acc[mf][nf][1]),
                          "+f"(acc[mf][nf][2]), "+f"(acc[mf][nf][3])
                        : "r"(a_[mf][0]), "r"(a_[mf][1]), "r"(a_[mf][2]), "r"(a_[mf][3]),
                          "r"(b_[nf][0]), "r"(b_[nf][1]));
                }
        }
        __syncthreads();
    }

    // ---- fused LSTM cell epilogue ----
    // cols are gate-interleaved: col = 4j+gate. Even lane of each pair holds
    // (i,f), odd holds (g,o); one shfl_xor(1) exchange gives each lane all 4
    // gates: even does row r, odd does row r+8.
    __nv_bfloat16* Xh_w = g_Xh[wr];
    __nv_bfloat16* Xl_w = g_Xl[wr];
    const bool odd = lane & 1;

    #pragma unroll
    for (int mf = 0; mf < 4; mf++) {
        #pragma unroll
        for (int nf = 0; nf < 4; nf++) {
            int rowbase = bm + warp_m * 64 + mf * 16 + (lane >> 2);
            int colbase = bn + warp_n * 32 + nf * 8 + (lane & 3) * 2;
            int j = colbase >> 2;

            float p0 = __shfl_xor_sync(0xffffffffu, acc[mf][nf][0], 1);
            float p1 = __shfl_xor_sync(0xffffffffu, acc[mf][nf][1], 1);
            float p2 = __shfl_xor_sync(0xffffffffu, acc[mf][nf][2], 1);
            float p3 = __shfl_xor_sync(0xffffffffu, acc[mf][nf][3], 1);

            float gi, gf, gg, go;
            int r;
            if (!odd) { gi = acc[mf][nf][0]; gf = acc[mf][nf][1]; gg = p0; go = p1; r = rowbase; }
            else      { gi = p2;             gf = p3;             gg = acc[mf][nf][2]; go = acc[mf][nf][3]; r = rowbase + 8; }

            float4 bs = *(const float4*)&g_bias[j * 4];
            gi += bs.x; gf += bs.y; gg += bs.z; go += bs.w;

            float c  = g_c[r * Hd + j];
            float cn = sigm(gf) * c + sigm(gi) * ftanh(gg);
            g_c[r * Hd + j] = cn;
            float hn = sigm(go) * ftanh(cn);

            __nv_bfloat16 hi, lo;
            split_bf16(hn, hi, lo);
            Xh_w[r * KC + Od + j] = hi;
            Xl_w[r * KC + Od + j] = lo;
        }
    }
}

// ==========================================================================
// logits GEMM: logits[512,512] = h[512,1024] @ W_out[512,1024]^T
// (3 bf16-split passes). BM=32 BN=128 BK=32, 8 warps (2x4).
// ==========================================================================
#define NT_LOG 96   // 3 passes * 32 k-tiles

__global__ __launch_bounds__(256) void logits_mma(int wr) {
    __shared__ __align__(1024) unsigned char sm[3][10240];   // per stage: A 2KB | B 8KB

    const int tid  = threadIdx.x;
    const int wid  = tid >> 5;
    const int lane = tid & 31;
    const int warp_m = wid >> 2;     // 0..1 (16 rows each)
    const int warp_n = wid & 3;      // 0..3 (32 cols each)
    const int bm = blockIdx.y * 32;
    const int bn = blockIdx.x * 128;

    const __nv_bfloat16* Xh = g_Xh[wr];   // h written this step
    const __nv_bfloat16* Xl = g_Xl[wr];

    const unsigned sbase = (unsigned)__cvta_generic_to_shared(&sm[0][0]);

    // A tile: 32 rows x 64B = 128 chunks (threads 0..127)
    const int rAt = tid >> 2;            // row if tid<128
    const int kcA = tid & 3;
    const unsigned sOffA = SWZ((unsigned)(rAt * 64 + kcA * 16));
    // B tile: 128 rows x 64B = 512 chunks (2 per thread)
    const int rB0 = tid >> 2;
    const int rB1 = rB0 + 64;
    const unsigned sOffB0 = SWZ((unsigned)(rB0 * 64 + kcA * 16));
    const unsigned sOffB1 = SWZ((unsigned)(rB1 * 64 + kcA * 16));

    float acc[4][4];
    #pragma unroll
    for (int j = 0; j < 4; j++)
        #pragma unroll
        for (int q = 0; q < 4; q++) acc[j][q] = 0.0f;

    #define LOAD_TILE_L(I, BUF) do {                                            \
        int p_  = (I) / 32;                                                      \
        int k0_ = ((I) % 32) * 32;                                               \
        const __nv_bfloat16* Ag_ = (p_ == 2) ? Xl : Xh;                          \
        const __nv_bfloat16* Bg_ = (p_ == 1) ? g_Wol : g_Woh;                    \
        unsigned ab_ = sbase + (BUF) * 10240;                                    \
        unsigned bb_ = ab_ + 2048;                                               \
        if (tid < 128)                                                           \
            CP_ASYNC16(ab_ + sOffA, Ag_ + (size_t)(bm + rAt) * KC + Od + k0_ + kcA * 8); \
        CP_ASYNC16(bb_ + sOffB0, Bg_ + (size_t)(bn + rB0) * Hd + k0_ + kcA * 8); \
        CP_ASYNC16(bb_ + sOffB1, Bg_ + (size_t)(bn + rB1) * Hd + k0_ + kcA * 8); \
    } while (0)

    LOAD_TILE_L(0, 0); CP_COMMIT;
    LOAD_TILE_L(1, 1); CP_COMMIT;

    for (int it = 0; it < NT_LOG; it++) {
        const int buf = it % 3;
        if (it + 2 < NT_LOG) {
            LOAD_TILE_L(it + 2, (it + 2) % 3);
            CP_COMMIT;
            CP_WAIT2;
        } else if (it + 1 < NT_LOG) {
            CP_WAIT1;
        } else {
            CP_WAIT0;
        }
        __syncthreads();

        const unsigned ab = sbase + buf * 10240;
        const unsigned bb = ab + 2048;

        #pragma unroll
        for (int kk = 0; kk < 2; kk++) {
            unsigned a_[4];
            {
                unsigned byte = (warp_m * 16 + (lane & 15)) * 64 + kk * 32 + (lane >> 4) * 16;
                unsigned addr = ab + SWZ(byte);
                asm volatile("ldmatrix.sync.aligned.m8n8.x4.shared.b16 {%0,%1,%2,%3}, [%4];"
                             : "=r"(a_[0]), "=r"(a_[1]), "=r"(a_[2]), "=r"(a_[3])
                             : "r"(addr));
            }
            unsigned b_[4][2];
            #pragma unroll
            for (int pr = 0; pr < 2; pr++) {
                unsigned n = warp_n * 32 + pr * 16 + (lane & 7) + ((lane >> 4) & 1) * 8;
                unsigned byte = n * 64 + kk * 32 + ((lane >> 3) & 1) * 16;
                unsigned addr = bb + SWZ(byte);
                unsigned r0, r1, r2, r3;
                asm volatile("ldmatrix.sync.aligned.m8n8.x4.shared.b16 {%0,%1,%2,%3}, [%4];"
                             : "=r"(r0), "=r"(r1), "=r"(r2), "=r"(r3)
                             : "r"(addr));
                b_[2 * pr][0] = r0;      b_[2 * pr][1] = r1;
                b_[2 * pr + 1][0] = r2;  b_[2 * pr + 1][1] = r3;
            }
            #pragma unroll
            for (int nf = 0; nf < 4; nf++) {
                asm volatile(
                    "mma.sync.aligned.m16n8k16.row.col.f32.bf16.bf16.f32 "
                    "{%0,%1,%2,%3}, {%4,%5,%6,%7}, {%8,%9}, {%0,%1,%2,%3};"
                    : "+f"(acc[nf][0]), "+f"(acc[nf][1]), "+f"(acc[nf][2]), "+f"(acc[nf][3])
                    : "r"(a_[0]), "r"(a_[1]), "r"(a_[2]), "r"(a_[3]),
                      "r"(b_[nf][0]), "r"(b_[nf][1]));
            }
        }
        __syncthreads();
    }

    #pragma unroll
    for (int nf = 0; nf < 4; nf++) {
        int row = bm + warp_m * 16 + (lane >> 2);
        int col = bn + warp_n * 32 + nf * 8 + (lane & 3) * 2;
        *(float2*)&g_logits[(size_t)row * Od + col] = make_float2(acc[nf][0], acc[nf][1]);
        *(float2*)&g_logits[(size_t)(row + 8) * Od + col] = make_float2(acc[nf][2], acc[nf][3]);
    }
}

// ==========================================================================
// softmax + feedback: y = softmax(logits + b_out); write out + X buf (x part)
// ==========================================================================
#define RB 8

__global__ __launch_bounds__(256) void softmax_fb(const float* __restrict__ b_out,
                                                  float* __restrict__ out,
                                                  int step_off, int wr) {
    __shared__ float red[RB][8];

    const int b0 = blockIdx.x * RB;
    const int tid = threadIdx.x;
    const int warp = tid >> 5, lane = tid & 31;

    const int c0 = tid;
    const int c1 = tid + 256;
    const float bo0 = b_out[c0];
    const float bo1 = b_out[c1];

    float acc0[RB], acc1[RB];
    #pragma unroll
    for (int r = 0; r < RB; r++) {
        acc0[r] = g_logits[(size_t)(b0 + r) * Od + c0] + bo0;
        acc1[r] = g_logits[(size_t)(b0 + r) * Od + c1] + bo1;
    }

    #pragma unroll
    for (int r = 0; r < RB; r++) {
        float mm = fmaxf(acc0[r], acc1[r]);
        #pragma unroll
        for (int o = 16; o; o >>= 1) mm = fmaxf(mm, __shfl_xor_sync(0xffffffffu, mm, o));
        if (lane == 0) red[r][warp] = mm;
    }
    __syncthreads();
    float m[RB];
    #pragma unroll
    for (int r = 0; r < RB; r++) {
        float mm = red[r][0];
        #pragma unroll
        for (int w = 1; w < 8; w++) mm = fmaxf(mm, red[r][w]);
        m[r] = mm;
    }
    __syncthreads();

    #pragma unroll
    for (int r = 0; r < RB; r++) {
        acc0[r] = expf(acc0[r] - m[r]);
        acc1[r] = expf(acc1[r] - m[r]);
        float ss = acc0[r] + acc1[r];
        #pragma unroll
        for (int o = 16; o; o >>= 1) ss += __shfl_xor_sync(0xffffffffu, ss, o);
        if (lane == 0) red[r][warp] = ss;
    }
    __syncthreads();

    __nv_bfloat16* Xh_w = g_Xh[wr];
    __nv_bfloat16* Xl_w = g_Xl[wr];

    #pragma unroll
    for (int r = 0; r < RB; r++) {
        float ss = 0.0f;
        #pragma unroll
        for (int w = 0; w < 8; w++) ss += red[r][w];
        float inv = 1.0f / ss;
        float y0 = acc0[r] * inv;
        float y1 = acc1[r] * inv;
        int b = b0 + r;
        out[step_off + b * Od + c0] = y0;
        out[step_off + b * Od + c1] = y1;
        __nv_bfloat16 hi, lo;
        split_bf16(y0, hi, lo);
        Xh_w[b * KC + c0] = hi;  Xl_w[b * KC + c0] = lo;
        split_bf16(y1, hi, lo);
        Xh_w[b * KC + c1] = hi;  Xl_w[b * KC + c1] = lo;
    }
}

// ---------------- launcher ------------------------------------------------
extern "C" void kernel_launch(void* const* d_in, const int* in_sizes, int n_in,
                              void* d_out, int out_size) {
    const float* h0    = (const float*)d_in[0];
    const float* c0    = (const float*)d_in[1];
    const float* W_ih  = (const float*)d_in[2];
    const float* W_hh  = (const float*)d_in[3];
    const float* b_ih  = (const float*)d_in[4];
    const float* b_hh  = (const float*)d_in[5];
    const float* W_out = (const float*)d_in[6];
    const float* b_out = (const float*)d_in[7];
    float* out = (float*)d_out;

    const int T = out_size / (Bsz * Od);

    prep_weights<<<(G4 * KC + 255) / 256, 256>>>(W_ih, W_hh, b_ih, b_hh, W_out);
    prep_state<<<(Bsz * Hd + 255) / 256, 256>>>(h0, c0);

    dim3 ggrid(G4 / 128, Bsz / 128);   // (32, 4) = 128 blocks
    dim3 lgrid(Od / 128, Bsz / 32);    // (4, 16) = 64 blocks
    for (int t = 0; t < T; t++) {
        int rd = t & 1, wr = rd ^ 1;
        gemm_gates_mma<<<ggrid, 256>>>(rd, wr);
        logits_mma<<<lgrid, 256>>>(wr);
        softmax_fb<<<Bsz / RB, 256>>>(b_out, out, (T - 1 - t) * Bsz * Od, wr);
    }
}

// round 5
// speedup vs baseline: 3.3061x; 1.4959x over previous
#include <cuda_runtime.h>
#include <cuda_bf16.h>
#include <math.h>

#define Bsz 512
#define Hd  1024
#define Od  512
#define KC  1536   // Od + Hd
#define G4  4096   // 4*Hd
#define KSPLIT 8

// ---------------- scratch ----------------
__device__ __nv_bfloat16 g_Xh[2][Bsz * KC];   // ping-pong [buf][B][KC]
__device__ __nv_bfloat16 g_Xl[2][Bsz * KC];
__device__ __nv_bfloat16 g_Wh[G4 * KC];       // gate-interleaved [4j+gate][k]
__device__ __nv_bfloat16 g_Wl[G4 * KC];
__device__ __nv_bfloat16 g_Woh[Od * Hd];
__device__ __nv_bfloat16 g_Wol[Od * Hd];
__device__ float g_c[Bsz * Hd];               // [b][j]
__device__ float g_bias[G4];                  // gate-interleaved
__device__ float g_lp[KSPLIT][Bsz * Od];      // logits split-K partials

__device__ __forceinline__ void split_bf16(float v, __nv_bfloat16& hi, __nv_bfloat16& lo) {
    hi = __float2bfloat16(v);
    lo = __float2bfloat16(v - __bfloat162float(hi));
}
__device__ __forceinline__ float sigm(float x) { return 1.0f / (1.0f + __expf(-x)); }
__device__ __forceinline__ float ftanh(float x) { return 1.0f - 2.0f / (__expf(2.0f * x) + 1.0f); }

// ---------------- prep -------------------
__global__ void prep_weights(const float* __restrict__ W_ih,
                             const float* __restrict__ W_hh,
                             const float* __restrict__ b_ih,
                             const float* __restrict__ b_hh,
                             const float* __restrict__ W_out) {
    int idx = blockIdx.x * blockDim.x + threadIdx.x;
    if (idx < G4 * KC) {
        int r = idx / KC;
        int k = idx - r * KC;
        int j = r >> 2, gate = r & 3;
        int orow = gate * Hd + j;
        float w = (k < Od) ? W_ih[orow * Od + k] : W_hh[orow * Hd + (k - Od)];
        __nv_bfloat16 hi, lo;
        split_bf16(w, hi, lo);
        g_Wh[idx] = hi;
        g_Wl[idx] = lo;
    }
    if (idx < G4) {
        int j = idx >> 2, gate = idx & 3;
        g_bias[idx] = b_ih[gate * Hd + j] + b_hh[gate * Hd + j];
    }
    if (idx < Od * Hd) {
        __nv_bfloat16 hi, lo;
        split_bf16(W_out[idx], hi, lo);
        g_Woh[idx] = hi;
        g_Wol[idx] = lo;
    }
}

__global__ void prep_state(const float* __restrict__ h0,
                           const float* __restrict__ c0) {
    int idx = blockIdx.x * blockDim.x + threadIdx.x;
    if (idx < Bsz * Hd) {
        int b = idx >> 10;
        int j = idx & (Hd - 1);
        __nv_bfloat16 hi, lo;
        split_bf16(h0[idx], hi, lo);
        g_Xh[0][b * KC + Od + j] = hi;
        g_Xl[0][b * KC + Od + j] = lo;
        g_c[idx] = c0[idx];
    }
    if (idx < Bsz * Od) {
        int b = idx >> 9;
        int k = idx & (Od - 1);
        g_Xh[0][b * KC + k] = __float2bfloat16(0.0f);
        g_Xl[0][b * KC + k] = __float2bfloat16(0.0f);
    }
}

// ---------------- asm helpers --------------------------------------------
#define SWZ(b) ((b) ^ (((b) >> 3) & 0x30))   // 64B-row XOR swizzle

#define CP_ASYNC16(dst, src) asm volatile("cp.async.cg.shared.global [%0], [%1], 16;\n" :: "r"(dst), "l"(src))
#define CP_COMMIT            asm volatile("cp.async.commit_group;\n")
#define CP_WAIT2             asm volatile("cp.async.wait_group 2;\n")
#define CP_WAIT1             asm volatile("cp.async.wait_group 1;\n")
#define CP_WAIT0             asm volatile("cp.async.wait_group 0;\n")

#define LDSM_X4(d0, d1, d2, d3, addr) \
    asm volatile("ldmatrix.sync.aligned.m8n8.x4.shared.b16 {%0,%1,%2,%3}, [%4];" \
                 : "=r"(d0), "=r"(d1), "=r"(d2), "=r"(d3) : "r"(addr))

#define MMA_BF16(acc, a, b) \
    asm volatile( \
        "mma.sync.aligned.m16n8k16.row.col.f32.bf16.bf16.f32 " \
        "{%0,%1,%2,%3}, {%4,%5,%6,%7}, {%8,%9}, {%0,%1,%2,%3};" \
        : "+f"((acc)[0]), "+f"((acc)[1]), "+f"((acc)[2]), "+f"((acc)[3]) \
        : "r"((a)[0]), "r"((a)[1]), "r"((a)[2]), "r"((a)[3]), \
          "r"((b)[0]), "r"((b)[1]))

#define STAGE_G 32768
#define SMEM_G  (3 * STAGE_G)    // 96 KB

// ==========================================================================
// gates GEMM + fused cell update.
// gates[512,4096] = X·W^T, X=[Xh;Xl], W=[Wh;Wl], 3 products into one acc:
//   Xh·Wh + Xh·Wl + Xl·Wh, fp32 accum. BM=BN=128, BK=32, 48 k-iters.
// Stage layout (32KB): Xh | Xl | Wh | Wl, 8KB each (128 rows x 64B swizzled).
// ==========================================================================
#define NT_G 48

__global__ __launch_bounds__(256) void gates_mma(int rd, int wr) {
    extern __shared__ __align__(1024) unsigned char smg[];

    const int tid  = threadIdx.x;
    const int wid  = tid >> 5;
    const int lane = tid & 31;
    const int warp_m = wid >> 2;   // 0..1
    const int warp_n = wid & 3;    // 0..3
    const int bm = blockIdx.y * 128;
    const int bn = blockIdx.x * 128;

    const __nv_bfloat16* Xh = g_Xh[rd];
    const __nv_bfloat16* Xl = g_Xl[rd];

    const unsigned sbase = (unsigned)__cvta_generic_to_shared(smg);

    const int rA0 = tid >> 2;        // 0..63
    const int rA1 = rA0 + 64;
    const int kc  = tid & 3;
    const unsigned sOff0 = SWZ((unsigned)(rA0 * 64 + kc * 16));
    const unsigned sOff1 = SWZ((unsigned)(rA1 * 64 + kc * 16));

    float acc[4][4][4];
    #pragma unroll
    for (int i = 0; i < 4; i++)
        #pragma unroll
        for (int j = 0; j < 4; j++)
            #pragma unroll
            for (int q = 0; q < 4; q++) acc[i][j][q] = 0.0f;

    #define LOADG(I, BUF) do {                                                \
        int k0_ = (I) * 32;                                                   \
        unsigned s_ = sbase + (BUF) * STAGE_G;                                \
        size_t a0_ = (size_t)(bm + rA0) * KC + k0_ + kc * 8;                  \
        size_t a1_ = (size_t)(bm + rA1) * KC + k0_ + kc * 8;                  \
        size_t b0_ = (size_t)(bn + rA0) * KC + k0_ + kc * 8;                  \
        size_t b1_ = (size_t)(bn + rA1) * KC + k0_ + kc * 8;                  \
        CP_ASYNC16(s_ + sOff0,          Xh   + a0_);                          \
        CP_ASYNC16(s_ + sOff1,          Xh   + a1_);                          \
        CP_ASYNC16(s_ + 8192  + sOff0,  Xl   + a0_);                          \
        CP_ASYNC16(s_ + 8192  + sOff1,  Xl   + a1_);                          \
        CP_ASYNC16(s_ + 16384 + sOff0,  g_Wh + b0_);                          \
        CP_ASYNC16(s_ + 16384 + sOff1,  g_Wh + b1_);                          \
        CP_ASYNC16(s_ + 24576 + sOff0,  g_Wl + b0_);                          \
        CP_ASYNC16(s_ + 24576 + sOff1,  g_Wl + b1_);                          \
        CP_COMMIT;                                                            \
    } while (0)

    LOADG(0, 0);
    LOADG(1, 1);

    for (int it = 0; it < NT_G; it++) {
        const int buf = it % 3;
        if (it + 2 < NT_G) {
            LOADG(it + 2, (it + 2) % 3);
            CP_WAIT2;
        } else if (it + 1 < NT_G) {
            CP_WAIT1;
        } else {
            CP_WAIT0;
        }
        __syncthreads();

        const unsigned sb = sbase + buf * STAGE_G;

        #pragma unroll
        for (int kk = 0; kk < 2; kk++) {
            const unsigned ar  = (unsigned)(lane & 15);
            const unsigned ahk = (unsigned)(lane >> 4);
            unsigned ah[4][4], al[4][4];
            #pragma unroll
            for (int mf = 0; mf < 4; mf++) {
                unsigned byte = (warp_m * 64 + mf * 16 + ar) * 64 + kk * 32 + ahk * 16;
                unsigned sw = SWZ(byte);
                LDSM_X4(ah[mf][0], ah[mf][1], ah[mf][2], ah[mf][3], sb + sw);
                LDSM_X4(al[mf][0], al[mf][1], al[mf][2], al[mf][3], sb + 8192 + sw);
            }
            unsigned bh[4][2], bl[4][2];
            #pragma unroll
            for (int pr = 0; pr < 2; pr++) {
                unsigned n = warp_n * 32 + pr * 16 + (lane & 7) + ((lane >> 4) & 1) * 8;
                unsigned byte = n * 64 + kk * 32 + ((lane >> 3) & 1) * 16;
                unsigned sw = SWZ(byte);
                unsigned r0, r1, r2, r3;
                LDSM_X4(r0, r1, r2, r3, sb + 16384 + sw);
                bh[2 * pr][0] = r0;      bh[2 * pr][1] = r1;
                bh[2 * pr + 1][0] = r2;  bh[2 * pr + 1][1] = r3;
                LDSM_X4(r0, r1, r2, r3, sb + 24576 + sw);
                bl[2 * pr][0] = r0;      bl[2 * pr][1] = r1;
                bl[2 * pr + 1][0] = r2;  bl[2 * pr + 1][1] = r3;
            }
            #pragma unroll
            for (int mf = 0; mf < 4; mf++)
                #pragma unroll
                for (int nf = 0; nf < 4; nf++)
                    MMA_BF16(acc[mf][nf], ah[mf], bh[nf]);
            #pragma unroll
            for (int mf = 0; mf < 4; mf++)
                #pragma unroll
                for (int nf = 0; nf < 4; nf++)
                    MMA_BF16(acc[mf][nf], ah[mf], bl[nf]);
            #pragma unroll
            for (int mf = 0; mf < 4; mf++)
                #pragma unroll
                for (int nf = 0; nf < 4; nf++)
                    MMA_BF16(acc[mf][nf], al[mf], bh[nf]);
        }
        __syncthreads();
    }

    // ---- fused LSTM cell epilogue (gate-interleaved cols, shfl exchange) ----
    __nv_bfloat16* Xh_w = g_Xh[wr];
    __nv_bfloat16* Xl_w = g_Xl[wr];
    const bool odd = lane & 1;

    #pragma unroll
    for (int mf = 0; mf < 4; mf++) {
        #pragma unroll
        for (int nf = 0; nf < 4; nf++) {
            int rowbase = bm + warp_m * 64 + mf * 16 + (lane >> 2);
            int colbase = bn + warp_n * 32 + nf * 8 + (lane & 3) * 2;
            int j = colbase >> 2;

            float p0 = __shfl_xor_sync(0xffffffffu, acc[mf][nf][0], 1);
            float p1 = __shfl_xor_sync(0xffffffffu, acc[mf][nf][1], 1);
            float p2 = __shfl_xor_sync(0xffffffffu, acc[mf][nf][2], 1);
            float p3 = __shfl_xor_sync(0xffffffffu, acc[mf][nf][3], 1);

            float gi, gf, gg, go;
            int r;
            if (!odd) { gi = acc[mf][nf][0]; gf = acc[mf][nf][1]; gg = p0; go = p1; r = rowbase; }
            else      { gi = p2;             gf = p3;             gg = acc[mf][nf][2]; go = acc[mf][nf][3]; r = rowbase + 8; }

            float4 bs = *(const float4*)&g_bias[j * 4];
            gi += bs.x; gf += bs.y; gg += bs.z; go += bs.w;

            float c  = g_c[r * Hd + j];
            float cn = sigm(gf) * c + sigm(gi) * ftanh(gg);
            g_c[r * Hd + j] = cn;
            float hn = sigm(go) * ftanh(cn);

            __nv_bfloat16 hi, lo;
            split_bf16(hn, hi, lo);
            Xh_w[r * KC + Od + j] = hi;
            Xl_w[r * KC + Od + j] = lo;
        }
    }
}

// ==========================================================================
// logits GEMM (split-K=8): g_lp[kz] = h·W_out^T partial over K-chunk of 128.
// BM=BN=128, BK=32, 4 k-iters. Grid (4, 4, 8) = 128 blocks.
// ==========================================================================
#define NT_L 4

__global__ __launch_bounds__(256) void logits_mma(int wr) {
    extern __shared__ __align__(1024) unsigned char sml[];

    const int tid  = threadIdx.x;
    const int wid  = tid >> 5;
    const int lane = tid & 31;
    const int warp_m = wid >> 2;
    const int warp_n = wid & 3;
    const int bm = blockIdx.y * 128;
    const int bn = blockIdx.x * 128;
    const int kz = blockIdx.z;
    const int kbase = kz * (Hd / KSPLIT);   // 128

    const __nv_bfloat16* Xh = g_Xh[wr];
    const __nv_bfloat16* Xl = g_Xl[wr];

    const unsigned sbase = (unsigned)__cvta_generic_to_shared(sml);

    const int rA0 = tid >> 2;
    const int rA1 = rA0 + 64;
    const int kc  = tid & 3;
    const unsigned sOff0 = SWZ((unsigned)(rA0 * 64 + kc * 16));
    const unsigned sOff1 = SWZ((unsigned)(rA1 * 64 + kc * 16));

    float acc[4][4][4];
    #pragma unroll
    for (int i = 0; i < 4; i++)
        #pragma unroll
        for (int j = 0; j < 4; j++)
            #pragma unroll
            for (int q = 0; q < 4; q++) acc[i][j][q] = 0.0f;

    #define LOADL(I, BUF) do {                                                \
        int k0_ = kbase + (I) * 32;                                           \
        unsigned s_ = sbase + (BUF) * STAGE_G;                                \
        size_t a0_ = (size_t)(bm + rA0) * KC + Od + k0_ + kc * 8;             \
        size_t a1_ = (size_t)(bm + rA1) * KC + Od + k0_ + kc * 8;             \
        size_t b0_ = (size_t)(bn + rA0) * Hd + k0_ + kc * 8;                  \
        size_t b1_ = (size_t)(bn + rA1) * Hd + k0_ + kc * 8;                  \
        CP_ASYNC16(s_ + sOff0,          Xh    + a0_);                         \
        CP_ASYNC16(s_ + sOff1,          Xh    + a1_);                         \
        CP_ASYNC16(s_ + 8192  + sOff0,  Xl    + a0_);                         \
        CP_ASYNC16(s_ + 8192  + sOff1,  Xl    + a1_);                         \
        CP_ASYNC16(s_ + 16384 + sOff0,  g_Woh + b0_);                         \
        CP_ASYNC16(s_ + 16384 + sOff1,  g_Woh + b1_);                         \
        CP_ASYNC16(s_ + 24576 + sOff0,  g_Wol + b0_);                         \
        CP_ASYNC16(s_ + 24576 + sOff1,  g_Wol + b1_);                         \
        CP_COMMIT;                                                            \
    } while (0)

    LOADL(0, 0);
    LOADL(1, 1);

    for (int it = 0; it < NT_L; it++) {
        const int buf = it % 3;
        if (it + 2 < NT_L) {
            LOADL(it + 2, (it + 2) % 3);
            CP_WAIT2;
        } else if (it + 1 < NT_L) {
            CP_WAIT1;
        } else {
            CP_WAIT0;
        }
        __syncthreads();

        const unsigned sb = sbase + buf * STAGE_G;

        #pragma unroll
        for (int kk = 0; kk < 2; kk++) {
            const unsigned ar  = (unsigned)(lane & 15);
            const unsigned ahk = (unsigned)(lane >> 4);
            unsigned ah[4][4], al[4][4];
            #pragma unroll
            for (int mf = 0; mf < 4; mf++) {
                unsigned byte = (warp_m * 64 + mf * 16 + ar) * 64 + kk * 32 + ahk * 16;
                unsigned sw = SWZ(byte);
                LDSM_X4(ah[mf][0], ah[mf][1], ah[mf][2], ah[mf][3], sb + sw);
                LDSM_X4(al[mf][0], al[mf][1], al[mf][2], al[mf][3], sb + 8192 + sw);
            }
            unsigned bh[4][2], bl[4][2];
            #pragma unroll
            for (int pr = 0; pr < 2; pr++) {
                unsigned n = warp_n * 32 + pr * 16 + (lane & 7) + ((lane >> 4) & 1) * 8;
                unsigned byte = n * 64 + kk * 32 + ((lane >> 3) & 1) * 16;
                unsigned sw = SWZ(byte);
                unsigned r0, r1, r2, r3;
                LDSM_X4(r0, r1, r2, r3, sb + 16384 + sw);
                bh[2 * pr][0] = r0;      bh[2 * pr][1] = r1;
                bh[2 * pr + 1][0] = r2;  bh[2 * pr + 1][1] = r3;
                LDSM_X4(r0, r1, r2, r3, sb + 24576 + sw);
                bl[2 * pr][0] = r0;      bl[2 * pr][1] = r1;
                bl[2 * pr + 1][0] = r2;  bl[2 * pr + 1][1] = r3;
            }
            #pragma unroll
            for (int mf = 0; mf < 4; mf++)
                #pragma unroll
                for (int nf = 0; nf < 4; nf++)
                    MMA_BF16(acc[mf][nf], ah[mf], bh[nf]);
            #pragma unroll
            for (int mf = 0; mf < 4; mf++)
                #pragma unroll
                for (int nf = 0; nf < 4; nf++)
                    MMA_BF16(acc[mf][nf], ah[mf], bl[nf]);
            #pragma unroll
            for (int mf = 0; mf < 4; mf++)
                #pragma unroll
                for (int nf = 0; nf < 4; nf++)
                    MMA_BF16(acc[mf][nf], al[mf], bh[nf]);
        }
        __syncthreads();
    }

    float* lp = g_lp[kz];
    #pragma unroll
    for (int mf = 0; mf < 4; mf++) {
        #pragma unroll
        for (int nf = 0; nf < 4; nf++) {
            int row = bm + warp_m * 64 + mf * 16 + (lane >> 2);
            int col = bn + warp_n * 32 + nf * 8 + (lane & 3) * 2;
            *(float2*)&lp[(size_t)row * Od + col] = make_float2(acc[mf][nf][0], acc[mf][nf][1]);
            *(float2*)&lp[(size_t)(row + 8) * Od + col] = make_float2(acc[mf][nf][2], acc[mf][nf][3]);
        }
    }
}

// ==========================================================================
// softmax + feedback (sums KSPLIT partials)
// ==========================================================================
#define RB 4

__global__ __launch_bounds__(256) void softmax_fb(const float* __restrict__ b_out,
                                                  float* __restrict__ out,
                                                  int step_off, int wr) {
    __shared__ float red[RB][8];

    const int b0 = blockIdx.x * RB;
    const int tid = threadIdx.x;
    const int warp = tid >> 5, lane = tid & 31;

    const int c0 = tid;
    const int c1 = tid + 256;
    const float bo0 = b_out[c0];
    const float bo1 = b_out[c1];

    float acc0[RB], acc1[RB];
    #pragma unroll
    for (int r = 0; r < RB; r++) {
        size_t i0 = (size_t)(b0 + r) * Od + c0;
        size_t i1 = (size_t)(b0 + r) * Od + c1;
        float s0 = bo0, s1 = bo1;
        #pragma unroll
        for (int z = 0; z < KSPLIT; z++) {
            s0 += g_lp[z][i0];
            s1 += g_lp[z][i1];
        }
        acc0[r] = s0;
        acc1[r] = s1;
    }

    #pragma unroll
    for (int r = 0; r < RB; r++) {
        float mm = fmaxf(acc0[r], acc1[r]);
        #pragma unroll
        for (int o = 16; o; o >>= 1) mm = fmaxf(mm, __shfl_xor_sync(0xffffffffu, mm, o));
        if (lane == 0) red[r][warp] = mm;
    }
    __syncthreads();
    float m[RB];
    #pragma unroll
    for (int r = 0; r < RB; r++) {
        float mm = red[r][0];
        #pragma unroll
        for (int w = 1; w < 8; w++) mm = fmaxf(mm, red[r][w]);
        m[r] = mm;
    }
    __syncthreads();

    #pragma unroll
    for (int r = 0; r < RB; r++) {
        acc0[r] = __expf(acc0[r] - m[r]);
        acc1[r] = __expf(acc1[r] - m[r]);
        float ss = acc0[r] + acc1[r];
        #pragma unroll
        for (int o = 16; o; o >>= 1) ss += __shfl_xor_sync(0xffffffffu, ss, o);
        if (lane == 0) red[r][warp] = ss;
    }
    __syncthreads();

    __nv_bfloat16* Xh_w = g_Xh[wr];
    __nv_bfloat16* Xl_w = g_Xl[wr];

    #pragma unroll
    for (int r = 0; r < RB; r++) {
        float ss = 0.0f;
        #pragma unroll
        for (int w = 0; w < 8; w++) ss += red[r][w];
        float inv = 1.0f / ss;
        float y0 = acc0[r] * inv;
        float y1 = acc1[r] * inv;
        int b = b0 + r;
        out[step_off + b * Od + c0] = y0;
        out[step_off + b * Od + c1] = y1;
        __nv_bfloat16 hi, lo;
        split_bf16(y0, hi, lo);
        Xh_w[b * KC + c0] = hi;  Xl_w[b * KC + c0] = lo;
        split_bf16(y1, hi, lo);
        Xh_w[b * KC + c1] = hi;  Xl_w[b * KC + c1] = lo;
    }
}

// ---------------- launcher ------------------------------------------------
extern "C" void kernel_launch(void* const* d_in, const int* in_sizes, int n_in,
                              void* d_out, int out_size) {
    const float* h0    = (const float*)d_in[0];
    const float* c0    = (const float*)d_in[1];
    const float* W_ih  = (const float*)d_in[2];
    const float* W_hh  = (const float*)d_in[3];
    const float* b_ih  = (const float*)d_in[4];
    const float* b_hh  = (const float*)d_in[5];
    const float* W_out = (const float*)d_in[6];
    const float* b_out = (const float*)d_in[7];
    float* out = (float*)d_out;

    const int T = out_size / (Bsz * Od);

    cudaFuncSetAttribute(gates_mma,  cudaFuncAttributeMaxDynamicSharedMemorySize, SMEM_G);
    cudaFuncSetAttribute(logits_mma, cudaFuncAttributeMaxDynamicSharedMemorySize, SMEM_G);

    prep_weights<<<(G4 * KC + 255) / 256, 256>>>(W_ih, W_hh, b_ih, b_hh, W_out);
    prep_state<<<(Bsz * Hd + 255) / 256, 256>>>(h0, c0);

    dim3 ggrid(G4 / 128, Bsz / 128);          // (32, 4) = 128 blocks
    dim3 lgrid(Od / 128, Bsz / 128, KSPLIT);  // (4, 4, 8) = 128 blocks
    for (int t = 0; t < T; t++) {
        int rd = t & 1, wr = rd ^ 1;
        gates_mma<<<ggrid, 256, SMEM_G>>>(rd, wr);
        logits_mma<<<lgrid, 256, SMEM_G>>>(wr);
        softmax_fb<<<Bsz / RB, 256>>>(b_out, out, (T - 1 - t) * Bsz * Od, wr);
    }
}